// round 6
// baseline (speedup 1.0000x reference)
#include <cuda_runtime.h>
#include <cooperative_groups.h>
namespace cg = cooperative_groups;

#define Bn 256
#define Sn 64
#define Dn 64
#define Fn 10
#define NCn 10
#define Pf 2016.0f
#define NT 256

// float offsets into dynamic smem (per-CTA, d-half layout)
#define OFF_E    0        // 64 x 64  full embeddings
#define OFF_U    4096     // 64 x 32  (d-half)
#define OFF_V    6144     // 64 x 32
#define OFF_FH   8192     // 64 x 32
#define OFF_W0   10240    // 65 x 32  staging: W1a-half, then fw1-half
#define OFF_W1   12320    // 64 x 32  staging: W1b-half
#define OFF_CW2  14368    // 32 x 10  cw2 rows of this half
#define OFF_FW2  14688    // 10 x 32  fw2 half, transposed [f][dl]
#define OFF_CC   15008    // 10 x 64  full cluster centers
#define OFF_FR   15648    // 64
#define OFF_SID  15712    // 64 (int)
#define OFF_HP   15776    // 32 x 32  pair partials
#define OFF_HS   16800    // 32
#define OFF_DIST 16832    // 32 x 10  own-token distances -> softmax
#define OFF_XPF  17152    // 64 x 10  partial freq feature (all rows, this d-half)
#define OFF_XCS  17792    // 10       partial csum
#define SMEM_FLOATS 17808 // 71,232 bytes

__device__ __forceinline__ void gemm_half(const float* __restrict__ sm, int woff,
                                          int s0, int dblk, float acc[2][4]) {
    const float4* E4 = (const float4*)(sm + OFF_E);
    const float4* W4 = (const float4*)(sm + woff);
#pragma unroll 4
    for (int kk = 0; kk < 16; ++kk) {
        float4 w0 = W4[(4 * kk + 0) * 8 + dblk];
        float4 w1 = W4[(4 * kk + 1) * 8 + dblk];
        float4 w2 = W4[(4 * kk + 2) * 8 + dblk];
        float4 w3 = W4[(4 * kk + 3) * 8 + dblk];
#pragma unroll
        for (int si = 0; si < 2; ++si) {
            float4 e = E4[(s0 + si) * 16 + kk];
            acc[si][0] += e.x * w0.x + e.y * w1.x + e.z * w2.x + e.w * w3.x;
            acc[si][1] += e.x * w0.y + e.y * w1.y + e.z * w2.y + e.w * w3.y;
            acc[si][2] += e.x * w0.z + e.y * w1.z + e.z * w2.z + e.w * w3.z;
            acc[si][3] += e.x * w0.w + e.y * w1.w + e.z * w2.w + e.w * w3.w;
        }
    }
}

__global__ __launch_bounds__(NT, 3) __cluster_dims__(2, 1, 1)
void cate_enc_kernel(const int* __restrict__ ids, const float* __restrict__ table,
                     const float* __restrict__ cw1, const float* __restrict__ cb1,
                     const float* __restrict__ cw2g, const float* __restrict__ cb2,
                     const float* __restrict__ fw1, const float* __restrict__ fb1,
                     const float* __restrict__ fw2g, const float* __restrict__ fb2,
                     const float* __restrict__ ccg, const float* __restrict__ catf,
                     const float* __restrict__ tot, float* __restrict__ out) {
    extern __shared__ float sm[];
    cg::cluster_group cluster = cg::this_cluster();
    const int t = threadIdx.x;
    const int h = blockIdx.x & 1;         // d-half / s-half index
    const int b = blockIdx.x >> 1;        // batch element
    const int qc0 = h * 8;                // float4 column offset of this half
    const int c0 = h * 32;

    const int dblk = t & 7;               // 0..7  float4 col within half
    const int sp   = t >> 3;              // 0..31
    const int s0   = sp * 2;

    // ---------- ph0: ids/freq + stage W1a-half + small weights ----------
    if (t < Sn) {
        int id = ids[b * Sn + t];
        ((int*)(sm + OFF_SID))[t] = id;
        sm[OFF_FR + t] = catf[id] / tot[0];
    }
    {
        float4* W0 = (float4*)(sm + OFF_W0);
        const float4* g4 = (const float4*)cw1;
#pragma unroll
        for (int c = 0; c < 2; ++c) {
            int lin = t + NT * c;                 // 0..511
            int r = lin >> 3, qq = lin & 7;
            W0[lin] = g4[r * 16 + qc0 + qq];      // W1a rows 0..63, half cols
        }
        if (t < 160) ((float4*)(sm + OFF_CC))[t] = ((const float4*)ccg)[t];
        for (int i = t; i < 320; i += NT) {
            int dl = (unsigned)i / 10u, f = i - dl * 10;
            sm[OFF_CW2 + i] = cw2g[(c0 + dl) * Fn + f];          // [dl][f]
            int f2 = i >> 5, dl2 = i & 31;
            sm[OFF_FW2 + i] = fw2g[(c0 + dl2) * Fn + f2];        // [f][dl]
        }
    }
    __syncthreads();

    // ---------- ph1: E gather (full) + stage W1b-half ----------
    {
        float4* E4 = (float4*)(sm + OFF_E);
        const float4* T4 = (const float4*)table;
        const int* sid = (const int*)(sm + OFF_SID);
#pragma unroll
        for (int c = 0; c < 4; ++c) {
            int lin = t + NT * c;
            int s = lin >> 4, q = lin & 15;
            E4[lin] = T4[sid[s] * 16 + q];
        }
        float4* W1 = (float4*)(sm + OFF_W1);
        const float4* g4 = (const float4*)cw1;
#pragma unroll
        for (int c = 0; c < 2; ++c) {
            int lin = t + NT * c;
            int r = lin >> 3, qq = lin & 7;
            W1[lin] = g4[(64 + r) * 16 + qc0 + qq];   // W1b rows 64..127
        }
    }
    __syncthreads();

    // ---------- ph2: U = E @ W1a_half + b1_half ----------
    {
        float acc[2][4] = {};
        gemm_half(sm, OFF_W0, s0, dblk, acc);
        float4 bv = ((const float4*)cb1)[qc0 + dblk];
        float4* U4 = (float4*)(sm + OFF_U);
#pragma unroll
        for (int si = 0; si < 2; ++si) {
            float4 o = {acc[si][0] + bv.x, acc[si][1] + bv.y,
                        acc[si][2] + bv.z, acc[si][3] + bv.w};
            U4[(s0 + si) * 8 + dblk] = o;
        }
    }
    __syncthreads();

    // ---------- ph3: V = E @ W1b_half ; stage fw1-half into W0 ----------
    {
        float4* W0 = (float4*)(sm + OFF_W0);
        const float4* g4 = (const float4*)fw1;        // [65][64]
#pragma unroll
        for (int c = 0; c < 2; ++c) {
            int lin = t + NT * c;
            int r = lin >> 3, qq = lin & 7;
            W0[lin] = g4[r * 16 + qc0 + qq];
        }
        if (t < 8) W0[512 + t] = g4[64 * 16 + qc0 + t];   // last row
    }
    {
        float acc[2][4] = {};
        gemm_half(sm, OFF_W1, s0, dblk, acc);
        float4* V4 = (float4*)(sm + OFF_V);
#pragma unroll
        for (int si = 0; si < 2; ++si) {
            float4 o = {acc[si][0], acc[si][1], acc[si][2], acc[si][3]};
            V4[(s0 + si) * 8 + dblk] = o;
        }
    }
    __syncthreads();

    // ---------- ph4: FH gemm ; balanced pair sum ; own-token distances ----------
    {
        float acc[2][4] = {};
        gemm_half(sm, OFF_W0, s0, dblk, acc);
        float4 fbv = ((const float4*)fb1)[qc0 + dblk];
        float4 wl  = ((const float4*)(sm + OFF_W0))[512 + dblk];
        float4* FH4 = (float4*)(sm + OFF_FH);
#pragma unroll
        for (int si = 0; si < 2; ++si) {
            float fq = sm[OFF_FR + s0 + si];
            float4 o;
            o.x = fmaxf(acc[si][0] + fq * wl.x + fbv.x, 0.f);
            o.y = fmaxf(acc[si][1] + fq * wl.y + fbv.y, 0.f);
            o.z = fmaxf(acc[si][2] + fq * wl.z + fbv.z, 0.f);
            o.w = fmaxf(acc[si][3] + fq * wl.w + fbv.w, 0.f);
            FH4[(s0 + si) * 8 + dblk] = o;
        }
    }
    __syncthreads();
    {   // pair sum over this d-half: thread (g=sp, dblk) owns i=g and i=63-g
        const float4* U4 = (const float4*)(sm + OFF_U);
        const float4* V4 = (const float4*)(sm + OFF_V);
        const int g = sp;
        float4 a = {0.f, 0.f, 0.f, 0.f};
        float4 u1 = U4[g * 8 + dblk];
#pragma unroll 4
        for (int j = g + 1; j < Sn; ++j) {
            float4 v = V4[j * 8 + dblk];
            a.x += fmaxf(u1.x + v.x, 0.f);
            a.y += fmaxf(u1.y + v.y, 0.f);
            a.z += fmaxf(u1.z + v.z, 0.f);
            a.w += fmaxf(u1.w + v.w, 0.f);
        }
        float4 u2 = U4[(63 - g) * 8 + dblk];
#pragma unroll 4
        for (int j = Sn - g; j < Sn; ++j) {
            float4 v = V4[j * 8 + dblk];
            a.x += fmaxf(u2.x + v.x, 0.f);
            a.y += fmaxf(u2.y + v.y, 0.f);
            a.z += fmaxf(u2.z + v.z, 0.f);
            a.w += fmaxf(u2.w + v.w, 0.f);
        }
        ((float4*)(sm + OFF_HP))[g * 8 + dblk] = a;
    }
    {   // distances for own 32 tokens (full-d dot), fused norms
        const float4* E4 = (const float4*)(sm + OFF_E);
        const float4* C4 = (const float4*)(sm + OFF_CC);
        for (int it = t; it < 32 * NCn; it += NT) {
            int srl = (unsigned)it / 10u, c = it - srl * 10;
            int s = c0 + srl;
            float dot = 0.f, e2 = 0.f, cc2 = 0.f;
#pragma unroll 4
            for (int kk = 0; kk < 16; ++kk) {
                float4 e = E4[s * 16 + kk];
                float4 cv = C4[c * 16 + kk];
                dot += e.x * cv.x + e.y * cv.y + e.z * cv.z + e.w * cv.w;
                e2  += e.x * e.x + e.y * e.y + e.z * e.z + e.w * e.w;
                cc2 += cv.x * cv.x + cv.y * cv.y + cv.z * cv.z + cv.w * cv.w;
            }
            sm[OFF_DIST + it] = sqrtf(fmaxf(e2 + cc2 - 2.f * dot, 0.f));
        }
    }
    __syncthreads();

    // ---------- ph5: partial freq dots (all 64 rows) ; Hsum ; softmax ----------
    {
        const float4* FH4 = (const float4*)(sm + OFF_FH);
        const float4* W2  = (const float4*)(sm + OFF_FW2);
        for (int it = t; it < Sn * Fn; it += NT) {
            int s = (unsigned)it / 10u, f = it - s * 10;
            float ff = 0.f;
#pragma unroll
            for (int kk = 0; kk < 8; ++kk) {
                float4 hh = FH4[s * 8 + kk];
                float4 w  = W2[f * 8 + kk];
                ff += hh.x * w.x + hh.y * w.y + hh.z * w.z + hh.w * w.w;
            }
            sm[OFF_XPF + it] = ff;
        }
    }
    if (t < 32) {
        const float* Hp = sm + OFF_HP;
        float s = 0.f;
#pragma unroll 8
        for (int g = 0; g < 32; ++g) s += Hp[g * 32 + t];
        sm[OFF_HS + t] = s;
    } else if (t < 64) {
        int srl = t - 32;
        float* dr = sm + OFF_DIST + srl * NCn;
        float mn = dr[0];
#pragma unroll
        for (int c = 1; c < NCn; ++c) mn = fminf(mn, dr[c]);
        float e[NCn]; float ssum = 0.f;
#pragma unroll
        for (int c = 0; c < NCn; ++c) { e[c] = __expf(mn - dr[c]); ssum += e[c]; }
        float inv = 1.f / ssum;
#pragma unroll
        for (int c = 0; c < NCn; ++c) dr[c] = e[c] * inv;
    }
    __syncthreads();

    // ---------- ph6: partial csum over this d-half ----------
    if (t < NCn) {
        float s = 0.f;
#pragma unroll 8
        for (int dl = 0; dl < 32; ++dl)
            s += sm[OFF_HS + dl] * sm[OFF_CW2 + dl * Fn + t];
        sm[OFF_XCS + t] = s;
    }

    // ---------- exchange: make xpf/xcs visible cluster-wide ----------
    cluster.sync();

    // ---------- ph7: combine halves, write own 32 rows ----------
    {
        const float* peer = (const float*)cluster.map_shared_rank((void*)sm, 1 - (blockIdx.x & 1));
        const float invP = 1.f / (Pf + 2.f);
        for (int it = t; it < 32 * Fn; it += NT) {
            int srl = (unsigned)it / 10u, f = it - srl * 10;
            int s = c0 + srl;
            float pf = sm[OFF_XPF + s * Fn + f] + peer[OFF_XPF + s * Fn + f];
            float cs = sm[OFF_XCS + f] + peer[OFF_XCS + f] + Pf * cb2[f];
            float o = (pf + fb2[f] + cs + sm[OFF_DIST + it]) * invP;
            out[b * (Sn * Fn) + s * Fn + f] = o;
        }
    }

    // keep smem alive until peer finishes reading
    cluster.sync();
}

extern "C" void kernel_launch(void* const* d_in, const int* in_sizes, int n_in,
                              void* d_out, int out_size) {
    const int*   ids  = (const int*)d_in[0];
    const float* tab  = (const float*)d_in[1];
    const float* cw1  = (const float*)d_in[2];
    const float* cb1  = (const float*)d_in[3];
    const float* cw2  = (const float*)d_in[4];
    const float* cb2  = (const float*)d_in[5];
    const float* fw1  = (const float*)d_in[6];
    const float* fb1  = (const float*)d_in[7];
    const float* fw2  = (const float*)d_in[8];
    const float* fb2  = (const float*)d_in[9];
    const float* cc   = (const float*)d_in[10];
    const float* catf = (const float*)d_in[11];
    const float* tot  = (const float*)d_in[12];
    float* out = (float*)d_out;

    cudaFuncSetAttribute(cate_enc_kernel,
                         cudaFuncAttributeMaxDynamicSharedMemorySize,
                         SMEM_FLOATS * (int)sizeof(float));
    cate_enc_kernel<<<Bn * 2, NT, SMEM_FLOATS * sizeof(float)>>>(
        ids, tab, cw1, cb1, cw2, cb2, fw1, fb1, fw2, fb2, cc, catf, tot, out);
}

// round 10
// speedup vs baseline: 1.1802x; 1.1802x over previous
#include <cuda_runtime.h>

#define Bn 256
#define Sn 64
#define Dn 64
#define Fn 10
#define NCn 10
#define Pf 2016.0f
#define NT 256

// float offsets into dynamic smem
#define OFF_E     0        // 64 x 64 embeddings
#define OFF_W     4096     // 64 x 192 fused weight panel [W1a|W1b|fw1]
                           //   aliased after GEMM: U @4096, V @8192, FH @12288
#define OFF_U     4096
#define OFF_V     8192
#define OFF_FH    12288
#define OFF_FW1L  16384    // 64  (fw1 row 64, the freq column)
#define OFF_CW2   16448    // 64 x 10
#define OFF_FW2T  17088    // 10 x 64 (transposed freq_w2)
#define OFF_CC    17728    // 10 x 64
#define OFF_FR    18368    // 64
#define OFF_SID   18432    // 64 (int)
#define OFF_HP    18496    // 16 x 64 pair partials
#define OFF_HS    19520    // 64
#define OFF_CSUM  19584    // 16
#define OFF_DIST  19600    // 64 x 10
#define SMEM_FLOATS 20240  // 80,960 B -> 2 CTAs/SM

__global__ __launch_bounds__(NT, 2)
void cate_enc_kernel(const int* __restrict__ ids, const float* __restrict__ table,
                     const float* __restrict__ cw1, const float* __restrict__ cb1,
                     const float* __restrict__ cw2g, const float* __restrict__ cb2,
                     const float* __restrict__ fw1, const float* __restrict__ fb1,
                     const float* __restrict__ fw2g, const float* __restrict__ fb2,
                     const float* __restrict__ ccg, const float* __restrict__ catf,
                     const float* __restrict__ tot, float* __restrict__ out) {
    extern __shared__ float sm[];
    const int t = threadIdx.x;
    const int b = blockIdx.x;
    const int dblk = t & 15;     // float4 column 0..15
    const int sp   = t >> 4;     // 0..15
    const int s0   = sp * 4;     // 4 seq rows per thread

    // ---------- ph0: ids/freq + stage fused weight panel + small weights ----------
    if (t < Sn) {
        int id = ids[b * Sn + t];
        ((int*)(sm + OFF_SID))[t] = id;
        sm[OFF_FR + t] = catf[id] / tot[0];
    }
    {
        float4* Wp = (float4*)(sm + OFF_W);          // [64][48] float4
        const float4* cw14 = (const float4*)cw1;     // [128][16]
        const float4* fw14 = (const float4*)fw1;     // [65][16]
#pragma unroll
        for (int u = 0; u < 12; ++u) {
            int i = t + NT * u;                      // 0..3071
            int r = i / 48, c = i - r * 48;
            float4 v;
            if (c < 16)       v = cw14[r * 16 + c];
            else if (c < 32)  v = cw14[(64 + r) * 16 + (c - 16)];
            else              v = fw14[r * 16 + (c - 32)];
            Wp[i] = v;
        }
        if (t < 16) ((float4*)(sm + OFF_FW1L))[t] = fw14[64 * 16 + t];
        if (t < 160) {                               // FIX: cw2 fully staged (160 float4)
            ((float4*)(sm + OFF_CC))[t]  = ((const float4*)ccg)[t];
            ((float4*)(sm + OFF_CW2))[t] = ((const float4*)cw2g)[t];
        }
        for (int i = t; i < Dn * Fn; i += NT) {      // fw2T[f*64+d] = fw2[d*10+f]
            int f = i >> 6, d = i & 63;
            sm[OFF_FW2T + i] = fw2g[d * Fn + f];
        }
    }
    __syncthreads();

    // ---------- ph1: gather E ----------
    {
        float4* E4 = (float4*)(sm + OFF_E);
        const float4* T4 = (const float4*)table;
        const int* sid = (const int*)(sm + OFF_SID);
#pragma unroll
        for (int c = 0; c < 4; ++c) {
            int lin = t + NT * c;
            int s = lin >> 4, q = lin & 15;
            E4[lin] = T4[sid[s] * 16 + q];
        }
    }
    __syncthreads();

    // ---------- ph2: fused GEMM  [U|V|FHpre] = E @ [W1a|W1b|fw1] ----------
    float acc[3][4][4];
#pragma unroll
    for (int g = 0; g < 3; ++g)
#pragma unroll
        for (int si = 0; si < 4; ++si)
#pragma unroll
            for (int c = 0; c < 4; ++c) acc[g][si][c] = 0.f;
    {
        const float4* E4 = (const float4*)(sm + OFF_E);
        const float4* W4 = (const float4*)(sm + OFF_W);   // [64][48]
        for (int kk = 0; kk < 16; ++kk) {
            float4 e0 = E4[(s0 + 0) * 16 + kk];
            float4 e1 = E4[(s0 + 1) * 16 + kk];
            float4 e2 = E4[(s0 + 2) * 16 + kk];
            float4 e3 = E4[(s0 + 3) * 16 + kk];
#pragma unroll
            for (int r = 0; r < 4; ++r) {
                float a0 = r == 0 ? e0.x : r == 1 ? e0.y : r == 2 ? e0.z : e0.w;
                float a1 = r == 0 ? e1.x : r == 1 ? e1.y : r == 2 ? e1.z : e1.w;
                float a2 = r == 0 ? e2.x : r == 1 ? e2.y : r == 2 ? e2.z : e2.w;
                float a3 = r == 0 ? e3.x : r == 1 ? e3.y : r == 2 ? e3.z : e3.w;
#pragma unroll
                for (int g = 0; g < 3; ++g) {
                    float4 w = W4[(4 * kk + r) * 48 + g * 16 + dblk];
                    acc[g][0][0] += a0 * w.x; acc[g][0][1] += a0 * w.y;
                    acc[g][0][2] += a0 * w.z; acc[g][0][3] += a0 * w.w;
                    acc[g][1][0] += a1 * w.x; acc[g][1][1] += a1 * w.y;
                    acc[g][1][2] += a1 * w.z; acc[g][1][3] += a1 * w.w;
                    acc[g][2][0] += a2 * w.x; acc[g][2][1] += a2 * w.y;
                    acc[g][2][2] += a2 * w.z; acc[g][2][3] += a2 * w.w;
                    acc[g][3][0] += a3 * w.x; acc[g][3][1] += a3 * w.y;
                    acc[g][3][2] += a3 * w.z; acc[g][3][3] += a3 * w.w;
                }
            }
        }
    }
    __syncthreads();   // all W reads done -> safe to alias

    // ---------- ph3: writeback U(+b1), V, FH=relu(.+fr*fw1L+fb1) over W panel ----------
    {
        float4 bv  = ((const float4*)cb1)[dblk];
        float4 fbv = ((const float4*)fb1)[dblk];
        float4 wl  = ((const float4*)(sm + OFF_FW1L))[dblk];
        float4* U4  = (float4*)(sm + OFF_U);
        float4* V4  = (float4*)(sm + OFF_V);
        float4* FH4 = (float4*)(sm + OFF_FH);
#pragma unroll
        for (int si = 0; si < 4; ++si) {
            float4 u = {acc[0][si][0] + bv.x, acc[0][si][1] + bv.y,
                        acc[0][si][2] + bv.z, acc[0][si][3] + bv.w};
            U4[(s0 + si) * 16 + dblk] = u;
            float4 v = {acc[1][si][0], acc[1][si][1], acc[1][si][2], acc[1][si][3]};
            V4[(s0 + si) * 16 + dblk] = v;
            float fq = sm[OFF_FR + s0 + si];
            float4 fh;
            fh.x = fmaxf(acc[2][si][0] + fq * wl.x + fbv.x, 0.f);
            fh.y = fmaxf(acc[2][si][1] + fq * wl.y + fbv.y, 0.f);
            fh.z = fmaxf(acc[2][si][2] + fq * wl.z + fbv.z, 0.f);
            fh.w = fmaxf(acc[2][si][3] + fq * wl.w + fbv.w, 0.f);
            FH4[(s0 + si) * 16 + dblk] = fh;
        }
    }
    __syncthreads();

    // ---------- ph4: balanced vectorized pair sum + distances ----------
    {
        const float4* U4 = (const float4*)(sm + OFF_U);
        const float4* V4 = (const float4*)(sm + OFF_V);
        const int g = sp;
        const int iset[4] = {g, 31 - g, 32 + g, 63 - g};   // 126 iters total
        float4 a = {0.f, 0.f, 0.f, 0.f};
#pragma unroll
        for (int q = 0; q < 4; ++q) {
            int i = iset[q];
            float4 u = U4[i * 16 + dblk];
#pragma unroll 4
            for (int j = i + 1; j < Sn; ++j) {
                float4 v = V4[j * 16 + dblk];
                a.x += fmaxf(u.x + v.x, 0.f);
                a.y += fmaxf(u.y + v.y, 0.f);
                a.z += fmaxf(u.z + v.z, 0.f);
                a.w += fmaxf(u.w + v.w, 0.f);
            }
        }
        ((float4*)(sm + OFF_HP))[g * 16 + dblk] = a;
    }
    {   // distances (640 items), fused norms
        const float4* E4 = (const float4*)(sm + OFF_E);
        const float4* C4 = (const float4*)(sm + OFF_CC);
        for (int it = t; it < Sn * NCn; it += NT) {
            int s = it / (unsigned)NCn, c = it - s * NCn;
            float dot = 0.f, e2 = 0.f, c2 = 0.f;
#pragma unroll 4
            for (int kk = 0; kk < 16; ++kk) {
                float4 e = E4[s * 16 + kk];
                float4 cv = C4[c * 16 + kk];
                dot += e.x * cv.x + e.y * cv.y + e.z * cv.z + e.w * cv.w;
                e2  += e.x * e.x + e.y * e.y + e.z * e.z + e.w * e.w;
                c2  += cv.x * cv.x + cv.y * cv.y + cv.z * cv.z + cv.w * cv.w;
            }
            sm[OFF_DIST + it] = sqrtf(fmaxf(e2 + c2 - 2.f * dot, 0.f));
        }
    }
    __syncthreads();

    // ---------- ph5: Hsum (t<64) ; softmax (64<=t<128) ----------
    if (t < Sn) {
        const float* Hp = sm + OFF_HP;
        float s = 0.f;
#pragma unroll
        for (int g = 0; g < 16; ++g) s += Hp[g * Dn + t];
        sm[OFF_HS + t] = s;
    } else if (t < 2 * Sn) {
        int s = t - Sn;
        float* dr = sm + OFF_DIST + s * NCn;
        float mn = dr[0];
#pragma unroll
        for (int c = 1; c < NCn; ++c) mn = fminf(mn, dr[c]);
        float e[NCn]; float ssum = 0.f;
#pragma unroll
        for (int c = 0; c < NCn; ++c) { e[c] = __expf(mn - dr[c]); ssum += e[c]; }
        float inv = 1.f / ssum;
#pragma unroll
        for (int c = 0; c < NCn; ++c) dr[c] = e[c] * inv;
    }
    __syncthreads();

    // ---------- ph6: csum ----------
    if (t < NCn) {
        float s = 0.f;
#pragma unroll 8
        for (int d = 0; d < Dn; ++d) s += sm[OFF_HS + d] * sm[OFF_CW2 + d * Fn + t];
        sm[OFF_CSUM + t] = s + Pf * cb2[t];
    }
    __syncthreads();

    // ---------- ph7: final output ----------
    const float invP = 1.f / (Pf + 2.f);
    const float4* FH4 = (const float4*)(sm + OFF_FH);
    const float4* W2T = (const float4*)(sm + OFF_FW2T);
    for (int it = t; it < Sn * Fn; it += NT) {
        int s = it / (unsigned)Fn, f = it - s * Fn;
        float ff = 0.f;
#pragma unroll 4
        for (int kk = 0; kk < 16; ++kk) {
            float4 h = FH4[s * 16 + kk];
            float4 w = W2T[f * 16 + kk];
            ff += h.x * w.x + h.y * w.y + h.z * w.z + h.w * w.w;
        }
        out[b * (Sn * Fn) + it] = (ff + fb2[f] + sm[OFF_CSUM + f] + sm[OFF_DIST + it]) * invP;
    }
}

extern "C" void kernel_launch(void* const* d_in, const int* in_sizes, int n_in,
                              void* d_out, int out_size) {
    const int*   ids  = (const int*)d_in[0];
    const float* tab  = (const float*)d_in[1];
    const float* cw1  = (const float*)d_in[2];
    const float* cb1  = (const float*)d_in[3];
    const float* cw2  = (const float*)d_in[4];
    const float* cb2  = (const float*)d_in[5];
    const float* fw1  = (const float*)d_in[6];
    const float* fb1  = (const float*)d_in[7];
    const float* fw2  = (const float*)d_in[8];
    const float* fb2  = (const float*)d_in[9];
    const float* cc   = (const float*)d_in[10];
    const float* catf = (const float*)d_in[11];
    const float* tot  = (const float*)d_in[12];
    float* out = (float*)d_out;

    cudaFuncSetAttribute(cate_enc_kernel,
                         cudaFuncAttributeMaxDynamicSharedMemorySize,
                         SMEM_FLOATS * (int)sizeof(float));
    cate_enc_kernel<<<Bn, NT, SMEM_FLOATS * sizeof(float)>>>(
        ids, tab, cw1, cb1, cw2, cb2, fw1, fb1, fw2, fb2, cc, catf, tot, out);
}